// round 6
// baseline (speedup 1.0000x reference)
#include <cuda_runtime.h>

#define Hh 100
#define Ww 136
#define HW (Hh * Ww)        // 13600
#define OH (2 * Hh)         // 200
#define OW (2 * Ww)         // 272
#define OHW (OH * OW)       // 54400
#define NP 169
#define MAXI 512
#define BLKS_PER_INST 2

typedef unsigned long long ull;

__device__ float g_logits[MAXI * HW];
__device__ float g_inter[MAXI];
__device__ float g_ux[MAXI];
__device__ float g_ut[MAXI];

// ---- packed f32x2 helpers (sm_100+) ----
__device__ __forceinline__ ull pk2(float lo, float hi) {
    ull r; asm("mov.b64 %0, {%1,%2};" : "=l"(r) : "f"(lo), "f"(hi)); return r;
}
__device__ __forceinline__ ull fma2(ull a, ull b, ull c) {
    ull d; asm("fma.rn.f32x2 %0, %1, %2, %3;" : "=l"(d) : "l"(a), "l"(b), "l"(c)); return d;
}
__device__ __forceinline__ ull relu2(ull a) {
    float x, y;
    asm("mov.b64 {%0,%1}, %2;" : "=f"(x), "=f"(y) : "l"(a));
    x = fmaxf(x, 0.0f); y = fmaxf(y, 0.0f);
    ull r; asm("mov.b64 %0, {%1,%2};" : "=l"(r) : "f"(x), "f"(y)); return r;
}
__device__ __forceinline__ void upk2(ull a, float& x, float& y) {
    asm("mov.b64 {%0,%1}, %2;" : "=f"(x), "=f"(y) : "l"(a));
}

// ---------------------------------------------------------------------------
// Kernel A: dynamic mask head -> logits.
// Accumulator-centric, transposed weights, ILP=8 (4 f32x2 chains):
// 88 LDS.128 feed 608 fma2 per unit (1:6.9) and the live set stays ~130-170
// regs because f dies before a1 is allocated. 1 block/SM, 8 warps, but the
// per-warp instruction stream is now fma-dominated.
// ---------------------------------------------------------------------------
__global__ __launch_bounds__(256) void logits_kernel(
    const float* __restrict__ feats,
    const float* __restrict__ params,
    const float* __restrict__ locs,
    const int*   __restrict__ im_inds,
    const int*   __restrict__ fpn)
{
    const int inst = blockIdx.x / BLKS_PER_INST;
    const int part = blockIdx.x % BLKS_PER_INST;
    const int tid  = threadIdx.x;

    // transposed, duplicated (lo=hi) weights
    __shared__ __align__(16) ull st0[10][8];  // st0[c][j], c: 0=x,1=y,2..9=feat
    __shared__ __align__(16) ull st1[8][8];
    __shared__ __align__(16) ull st2[8];
    __shared__ __align__(16) ull sb0[8];
    __shared__ __align__(16) ull sb1[8];
    __shared__ ull sb2;

    for (int i = tid; i < NP; i += 256) {
        float w = params[inst * NP + i];
        ull d = pk2(w, w);
        if      (i < 80)  st0[i % 10][i / 10] = d;
        else if (i < 144) { int k = i - 80; st1[k & 7][k >> 3] = d; }
        else if (i < 152) st2[i - 144] = d;
        else if (i < 160) sb0[i - 152] = d;
        else if (i < 168) sb1[i - 160] = d;
        else              sb2 = d;
    }
    __syncthreads();

    const float cx = locs[inst * 2 + 0];
    const float cy = locs[inst * 2 + 1];
    const float inv_soi = 1.0f / (float)(8 << fpn[inst]);
    const float step = -8.0f * inv_soi;
    const float* __restrict__ fb = feats + (size_t)im_inds[inst] * 8 * HW;
    float* __restrict__ Lg = g_logits + (size_t)inst * HW;

    // 8-px units: HW/8 = 1700 (Ww = 17*8, units never cross rows)
    const int NU   = HW / 8;                 // 1700
    const int per  = NU / BLKS_PER_INST;     // 850
    const int ubeg = part * per;
    const int uend = ubeg + per;

    for (int u = ubeg + tid; u < uend; u += 256) {
        const int p  = u * 8;
        const int py = p / Ww;
        const int px = p - py * Ww;
        const float dyv = (cy - (float)(py * 8 + 4)) * inv_soi;
        const float dxb = (cx - (float)(px * 8 + 4)) * inv_soi;
        const ull dy2 = pk2(dyv, dyv);
        ull dxp[4];
        #pragma unroll
        for (int k = 0; k < 4; k++)
            dxp[k] = pk2(dxb + (float)(2 * k) * step, dxb + (float)(2 * k + 1) * step);

        ull f[4][8];
        #pragma unroll
        for (int c = 0; c < 8; c++) {
            float4 v0 = *(const float4*)&fb[c * HW + p];
            float4 v1 = *(const float4*)&fb[c * HW + p + 4];
            f[0][c] = pk2(v0.x, v0.y);
            f[1][c] = pk2(v0.z, v0.w);
            f[2][c] = pk2(v1.x, v1.y);
            f[3][c] = pk2(v1.z, v1.w);
        }

        // ---- layer 0: init bias + x,y terms ----
        ull a0[4][8];
        {
            const ulonglong2* bb = (const ulonglong2*)sb0;
            const ulonglong2* wx = (const ulonglong2*)st0[0];
            const ulonglong2* wy = (const ulonglong2*)st0[1];
            #pragma unroll
            for (int h = 0; h < 4; h++) {
                ulonglong2 b = bb[h], vx = wx[h], vy = wy[h];
                int j = 2 * h;
                ull ty0 = fma2(vy.x, dy2, b.x);
                ull ty1 = fma2(vy.y, dy2, b.y);
                #pragma unroll
                for (int k = 0; k < 4; k++) {
                    a0[k][j]     = fma2(vx.x, dxp[k], ty0);
                    a0[k][j + 1] = fma2(vx.y, dxp[k], ty1);
                }
            }
        }
        // feature channels: outer-product updates
        #pragma unroll 1
        for (int c = 0; c < 8; c++) {
            const ulonglong2* wc = (const ulonglong2*)st0[c + 2];
            #pragma unroll
            for (int h = 0; h < 4; h++) {
                ulonglong2 w = wc[h];
                int j = 2 * h;
                #pragma unroll
                for (int k = 0; k < 4; k++) {
                    a0[k][j]     = fma2(w.x, f[k][c], a0[k][j]);
                    a0[k][j + 1] = fma2(w.y, f[k][c], a0[k][j + 1]);
                }
            }
        }
        #pragma unroll
        for (int k = 0; k < 4; k++)
            #pragma unroll
            for (int j = 0; j < 8; j++) a0[k][j] = relu2(a0[k][j]);   // h0 in a0

        // ---- layer 1 ----
        ull a1[4][8];
        {
            const ulonglong2* bb = (const ulonglong2*)sb1;
            #pragma unroll
            for (int h = 0; h < 4; h++) {
                ulonglong2 b = bb[h];
                int j = 2 * h;
                #pragma unroll
                for (int k = 0; k < 4; k++) { a1[k][j] = b.x; a1[k][j + 1] = b.y; }
            }
        }
        #pragma unroll 1
        for (int c = 0; c < 8; c++) {
            const ulonglong2* wc = (const ulonglong2*)st1[c];
            #pragma unroll
            for (int h = 0; h < 4; h++) {
                ulonglong2 w = wc[h];
                int j = 2 * h;
                #pragma unroll
                for (int k = 0; k < 4; k++) {
                    a1[k][j]     = fma2(w.x, a0[k][c], a1[k][j]);
                    a1[k][j + 1] = fma2(w.y, a0[k][c], a1[k][j + 1]);
                }
            }
        }

        // ---- layer 2 (relu folded) ----
        {
            const ulonglong2* wc = (const ulonglong2*)st2;
            ull o[4];
            #pragma unroll
            for (int k = 0; k < 4; k++) o[k] = sb2;
            #pragma unroll
            for (int h = 0; h < 4; h++) {
                ulonglong2 w = wc[h];
                int j = 2 * h;
                #pragma unroll
                for (int k = 0; k < 4; k++) {
                    o[k] = fma2(w.x, relu2(a1[k][j]), o[k]);
                    o[k] = fma2(w.y, relu2(a1[k][j + 1]), o[k]);
                }
            }
            float r[8];
            upk2(o[0], r[0], r[1]);
            upk2(o[1], r[2], r[3]);
            upk2(o[2], r[4], r[5]);
            upk2(o[3], r[6], r[7]);
            *(float4*)&Lg[p]     = make_float4(r[0], r[1], r[2], r[3]);
            *(float4*)&Lg[p + 4] = make_float4(r[4], r[5], r[6], r[7]);
        }
    }
}

// ---------------------------------------------------------------------------
// Kernel B: 2x aligned-bilinear + sigmoid + dice partials.
// ---------------------------------------------------------------------------
__global__ __launch_bounds__(512) void dice_kernel(const float* __restrict__ gt)
{
    extern __shared__ float sL[];   // HW floats = 54.4 KB
    const int inst = blockIdx.x;
    const float* __restrict__ L = g_logits + (size_t)inst * HW;
    const float* __restrict__ T = gt + (size_t)inst * OHW;

    for (int i = threadIdx.x; i < HW; i += 512) sL[i] = L[i];
    __syncthreads();

    float si = 0.0f, sx = 0.0f, st = 0.0f;

    const int NQ = OHW / 4;
    for (int q = threadIdx.x; q < NQ; q += 512) {
        const int oy = q / (OW / 4);
        const int ox = (q - oy * (OW / 4)) * 4;
        const int j  = (oy > 0) ? (oy - 1) : 0;
        const int y0 = j >> 1;
        const int y1 = min(y0 + 1, Hh - 1);
        const float* r0 = sL + y0 * Ww;
        const float* r1 = sL + y1 * Ww;
        const bool vodd = (j & 1) != 0;

        const int i0 = (ox > 0) ? (ox - 1) : 0;
        float v[4];
        int ii[4] = { i0, ox, ox + 1, ox + 2 };
        if (!vodd) {
            #pragma unroll
            for (int k = 0; k < 4; k++) {
                int x0 = ii[k] >> 1;
                int x1 = min(x0 + 1, Ww - 1);
                float a = r0[x0];
                v[k] = (ii[k] & 1) ? 0.5f * (a + r0[x1]) : a;
            }
        } else {
            #pragma unroll
            for (int k = 0; k < 4; k++) {
                int x0 = ii[k] >> 1;
                int x1 = min(x0 + 1, Ww - 1);
                float a = r0[x0], b = r1[x0];
                v[k] = (ii[k] & 1) ? 0.25f * ((a + r0[x1]) + (b + r1[x1]))
                                   : 0.5f  * (a + b);
            }
        }

        const float4 t4 = __ldcs((const float4*)&T[oy * OW + ox]);
        const float tv[4] = { t4.x, t4.y, t4.z, t4.w };
        #pragma unroll
        for (int k = 0; k < 4; k++) {
            float s = __fdividef(1.0f, 1.0f + __expf(-v[k]));
            si = fmaf(s, tv[k], si);
            sx = fmaf(s, s, sx);
            st = fmaf(tv[k], tv[k], st);
        }
    }

    __shared__ float sm[3][16];
    int lane = threadIdx.x & 31;
    int wid  = threadIdx.x >> 5;
    #pragma unroll
    for (int o = 16; o; o >>= 1) {
        si += __shfl_down_sync(0xffffffffu, si, o);
        sx += __shfl_down_sync(0xffffffffu, sx, o);
        st += __shfl_down_sync(0xffffffffu, st, o);
    }
    if (lane == 0) { sm[0][wid] = si; sm[1][wid] = sx; sm[2][wid] = st; }
    __syncthreads();
    if (wid == 0) {
        si = (lane < 16) ? sm[0][lane] : 0.0f;
        sx = (lane < 16) ? sm[1][lane] : 0.0f;
        st = (lane < 16) ? sm[2][lane] : 0.0f;
        #pragma unroll
        for (int o = 8; o; o >>= 1) {
            si += __shfl_down_sync(0xffffffffu, si, o);
            sx += __shfl_down_sync(0xffffffffu, sx, o);
            st += __shfl_down_sync(0xffffffffu, st, o);
        }
        if (lane == 0) {
            g_inter[inst] = si;
            g_ux[inst]    = sx;
            g_ut[inst]    = st;
        }
    }
}

__global__ __launch_bounds__(512) void loss_kernel(float* __restrict__ out, int n)
{
    __shared__ float sm[16];
    float acc = 0.0f;
    for (int i = threadIdx.x; i < n; i += 512) {
        float u = g_ux[i] + g_ut[i] + 1e-5f;
        acc += 1.0f - 2.0f * g_inter[i] / u;
    }
    int lane = threadIdx.x & 31;
    int wid  = threadIdx.x >> 5;
    #pragma unroll
    for (int o = 16; o; o >>= 1) acc += __shfl_down_sync(0xffffffffu, acc, o);
    if (lane == 0) sm[wid] = acc;
    __syncthreads();
    if (wid == 0) {
        acc = (lane < 16) ? sm[lane] : 0.0f;
        #pragma unroll
        for (int o = 8; o; o >>= 1) acc += __shfl_down_sync(0xffffffffu, acc, o);
        if (lane == 0) out[0] = acc / (float)n;
    }
}

extern "C" void kernel_launch(void* const* d_in, const int* in_sizes, int n_in,
                              void* d_out, int out_size)
{
    const float* feats   = (const float*)d_in[0];
    const float* params  = (const float*)d_in[1];
    const float* locs    = (const float*)d_in[2];
    const float* gt      = (const float*)d_in[3];
    const int*   im_inds = (const int*)d_in[4];
    const int*   fpn     = (const int*)d_in[5];

    int n = in_sizes[1] / NP;
    if (n > MAXI) n = MAXI;

    cudaFuncSetAttribute(dice_kernel, cudaFuncAttributeMaxDynamicSharedMemorySize,
                         HW * (int)sizeof(float));

    logits_kernel<<<BLKS_PER_INST * n, 256>>>(feats, params, locs, im_inds, fpn);
    dice_kernel<<<n, 512, HW * sizeof(float)>>>(gt);
    loss_kernel<<<1, 512>>>((float*)d_out, n);
}

// round 7
// speedup vs baseline: 1.4775x; 1.4775x over previous
#include <cuda_runtime.h>

#define Hh 100
#define Ww 136
#define HW (Hh * Ww)        // 13600
#define OH (2 * Hh)         // 200
#define OW (2 * Ww)         // 272
#define OHW (OH * OW)       // 54400
#define NP 169
#define MAXI 512
#define BLKS_PER_INST 8

typedef unsigned long long ull;

__device__ float g_logits[MAXI * HW];
__device__ float g_inter[MAXI];
__device__ float g_ux[MAXI];
__device__ float g_ut[MAXI];

// ---- packed f32x2 helpers (sm_100+) ----
__device__ __forceinline__ ull pk2(float lo, float hi) {
    ull r; asm("mov.b64 %0, {%1,%2};" : "=l"(r) : "f"(lo), "f"(hi)); return r;
}
__device__ __forceinline__ ull fma2(ull a, ull b, ull c) {
    ull d; asm("fma.rn.f32x2 %0, %1, %2, %3;" : "=l"(d) : "l"(a), "l"(b), "l"(c)); return d;
}
__device__ __forceinline__ ull relu2(ull a) {
    float x, y;
    asm("mov.b64 {%0,%1}, %2;" : "=f"(x), "=f"(y) : "l"(a));
    x = fmaxf(x, 0.0f); y = fmaxf(y, 0.0f);
    ull r; asm("mov.b64 %0, {%1,%2};" : "=l"(r) : "f"(x), "f"(y)); return r;
}
__device__ __forceinline__ void upk2(ull a, float& x, float& y) {
    asm("mov.b64 {%0,%1}, %2;" : "=f"(x), "=f"(y) : "l"(a));
}

// ---------------------------------------------------------------------------
// Kernel A: dynamic mask head -> logits. Layer-centric ILP=4 (R3 body, proven
// 83us @ 8 warps), PLUS: per-iteration memory barrier to stop cross-iteration
// software pipelining (the 110->255 reg inflation), reg cap for 2 blocks/SM,
// and 8 blocks/instance for tail-wave efficiency.
// ---------------------------------------------------------------------------
__global__ __launch_bounds__(256, 2) void logits_kernel(
    const float* __restrict__ feats,
    const float* __restrict__ params,
    const float* __restrict__ locs,
    const int*   __restrict__ im_inds,
    const int*   __restrict__ fpn)
{
    const int inst = blockIdx.x / BLKS_PER_INST;
    const int part = blockIdx.x % BLKS_PER_INST;
    const int tid  = threadIdx.x;

    __shared__ __align__(16) ull sw0[8][12];   // [j][0..9]=w, [10]=bias
    __shared__ __align__(16) ull sw1[8][10];   // [j][0..7]=w, [8]=bias
    __shared__ __align__(16) ull sw2[10];      // [0..7]=w,   [8]=bias

    for (int i = tid; i < NP; i += 256) {
        float w = params[inst * NP + i];
        ull d = pk2(w, w);
        if      (i < 80)  sw0[i / 10][i % 10] = d;
        else if (i < 144) { int k = i - 80; sw1[k >> 3][k & 7] = d; }
        else if (i < 152) sw2[i - 144] = d;
        else if (i < 160) sw0[i - 152][10] = d;
        else if (i < 168) sw1[i - 160][8] = d;
        else              sw2[8] = d;
    }
    __syncthreads();

    const float cx = locs[inst * 2 + 0];
    const float cy = locs[inst * 2 + 1];
    const float inv_soi = 1.0f / (float)(8 << fpn[inst]);
    const float step = -8.0f * inv_soi;
    const float* __restrict__ fb = feats + (size_t)im_inds[inst] * 8 * HW;
    float* __restrict__ Lg = g_logits + (size_t)inst * HW;

    const int NQ   = HW / 4;                 // 3400 quads (Ww%4==0)
    const int per  = NQ / BLKS_PER_INST;     // 425
    const int qbeg = part * per;
    const int qend = qbeg + per;

    for (int q = qbeg + tid; q < qend; q += 256) {
        const int p  = q * 4;
        const int py = p / Ww;
        const int px = p - py * Ww;
        const float dyv = (cy - (float)(py * 8 + 4)) * inv_soi;
        const float dxb = (cx - (float)(px * 8 + 4)) * inv_soi;
        const ull dy2 = pk2(dyv, dyv);
        const ull dx0 = pk2(dxb, dxb + step);
        const ull dx1 = pk2(dxb + 2.0f * step, dxb + 3.0f * step);

        ull f0[8], f1[8];
        #pragma unroll
        for (int c = 0; c < 8; c++) {
            float4 v = *(const float4*)&fb[c * HW + p];
            f0[c] = pk2(v.x, v.y);
            f1[c] = pk2(v.z, v.w);
        }

        // layer 0: 10 -> 8, relu
        ull h0a[8], h0b[8];
        #pragma unroll
        for (int j = 0; j < 8; j++) {
            const ulonglong2* r = (const ulonglong2*)sw0[j];
            ulonglong2 wA = r[0], wB = r[1], wC = r[2], wD = r[3], wE = r[4];
            ull bias = sw0[j][10];
            ull a0 = fma2(wA.y, dy2, bias);  a0 = fma2(wA.x, dx0, a0);
            ull a1 = fma2(wA.y, dy2, bias);  a1 = fma2(wA.x, dx1, a1);
            a0 = fma2(wB.x, f0[0], a0);  a1 = fma2(wB.x, f1[0], a1);
            a0 = fma2(wB.y, f0[1], a0);  a1 = fma2(wB.y, f1[1], a1);
            a0 = fma2(wC.x, f0[2], a0);  a1 = fma2(wC.x, f1[2], a1);
            a0 = fma2(wC.y, f0[3], a0);  a1 = fma2(wC.y, f1[3], a1);
            a0 = fma2(wD.x, f0[4], a0);  a1 = fma2(wD.x, f1[4], a1);
            a0 = fma2(wD.y, f0[5], a0);  a1 = fma2(wD.y, f1[5], a1);
            a0 = fma2(wE.x, f0[6], a0);  a1 = fma2(wE.x, f1[6], a1);
            a0 = fma2(wE.y, f0[7], a0);  a1 = fma2(wE.y, f1[7], a1);
            h0a[j] = relu2(a0);
            h0b[j] = relu2(a1);
        }

        // layer 1: 8 -> 8, relu
        ull h1a[8], h1b[8];
        #pragma unroll
        for (int j = 0; j < 8; j++) {
            const ulonglong2* r = (const ulonglong2*)sw1[j];
            ulonglong2 wA = r[0], wB = r[1], wC = r[2], wD = r[3];
            ull bias = sw1[j][8];
            ull a0 = fma2(wA.x, h0a[0], bias);  ull a1 = fma2(wA.x, h0b[0], bias);
            a0 = fma2(wA.y, h0a[1], a0);  a1 = fma2(wA.y, h0b[1], a1);
            a0 = fma2(wB.x, h0a[2], a0);  a1 = fma2(wB.x, h0b[2], a1);
            a0 = fma2(wB.y, h0a[3], a0);  a1 = fma2(wB.y, h0b[3], a1);
            a0 = fma2(wC.x, h0a[4], a0);  a1 = fma2(wC.x, h0b[4], a1);
            a0 = fma2(wC.y, h0a[5], a0);  a1 = fma2(wC.y, h0b[5], a1);
            a0 = fma2(wD.x, h0a[6], a0);  a1 = fma2(wD.x, h0b[6], a1);
            a0 = fma2(wD.y, h0a[7], a0);  a1 = fma2(wD.y, h0b[7], a1);
            h1a[j] = relu2(a0);
            h1b[j] = relu2(a1);
        }

        // layer 2: 8 -> 1
        {
            const ulonglong2* r = (const ulonglong2*)sw2;
            ulonglong2 wA = r[0], wB = r[1], wC = r[2], wD = r[3];
            ull bias = sw2[8];
            ull a0 = fma2(wA.x, h1a[0], bias);  ull a1 = fma2(wA.x, h1b[0], bias);
            a0 = fma2(wA.y, h1a[1], a0);  a1 = fma2(wA.y, h1b[1], a1);
            a0 = fma2(wB.x, h1a[2], a0);  a1 = fma2(wB.x, h1b[2], a1);
            a0 = fma2(wB.y, h1a[3], a0);  a1 = fma2(wB.y, h1b[3], a1);
            a0 = fma2(wC.x, h1a[4], a0);  a1 = fma2(wC.x, h1b[4], a1);
            a0 = fma2(wC.y, h1a[5], a0);  a1 = fma2(wC.y, h1b[5], a1);
            a0 = fma2(wD.x, h1a[6], a0);  a1 = fma2(wD.x, h1b[6], a1);
            a0 = fma2(wD.y, h1a[7], a0);  a1 = fma2(wD.y, h1b[7], a1);
            float4 o;
            upk2(a0, o.x, o.y);
            upk2(a1, o.z, o.w);
            *(float4*)&Lg[p] = o;
        }

        // Hard fence: stop ptxas from software-pipelining the next iteration's
        // ~90 LDS/LDG into this one (the 110->255 register inflation).
        asm volatile("" ::: "memory");
    }
}

// ---------------------------------------------------------------------------
// Kernel B: 2x aligned-bilinear + sigmoid + dice partials.
// ---------------------------------------------------------------------------
__global__ __launch_bounds__(512) void dice_kernel(const float* __restrict__ gt)
{
    extern __shared__ float sL[];   // HW floats = 54.4 KB
    const int inst = blockIdx.x;
    const float* __restrict__ L = g_logits + (size_t)inst * HW;
    const float* __restrict__ T = gt + (size_t)inst * OHW;

    for (int i = threadIdx.x; i < HW; i += 512) sL[i] = L[i];
    __syncthreads();

    float si = 0.0f, sx = 0.0f, st = 0.0f;

    const int NQ = OHW / 4;
    for (int q = threadIdx.x; q < NQ; q += 512) {
        const int oy = q / (OW / 4);
        const int ox = (q - oy * (OW / 4)) * 4;
        const int j  = (oy > 0) ? (oy - 1) : 0;
        const int y0 = j >> 1;
        const int y1 = min(y0 + 1, Hh - 1);
        const float* r0 = sL + y0 * Ww;
        const float* r1 = sL + y1 * Ww;
        const bool vodd = (j & 1) != 0;

        const int i0 = (ox > 0) ? (ox - 1) : 0;
        float v[4];
        int ii[4] = { i0, ox, ox + 1, ox + 2 };
        if (!vodd) {
            #pragma unroll
            for (int k = 0; k < 4; k++) {
                int x0 = ii[k] >> 1;
                int x1 = min(x0 + 1, Ww - 1);
                float a = r0[x0];
                v[k] = (ii[k] & 1) ? 0.5f * (a + r0[x1]) : a;
            }
        } else {
            #pragma unroll
            for (int k = 0; k < 4; k++) {
                int x0 = ii[k] >> 1;
                int x1 = min(x0 + 1, Ww - 1);
                float a = r0[x0], b = r1[x0];
                v[k] = (ii[k] & 1) ? 0.25f * ((a + r0[x1]) + (b + r1[x1]))
                                   : 0.5f  * (a + b);
            }
        }

        const float4 t4 = __ldcs((const float4*)&T[oy * OW + ox]);
        const float tv[4] = { t4.x, t4.y, t4.z, t4.w };
        #pragma unroll
        for (int k = 0; k < 4; k++) {
            float s = __fdividef(1.0f, 1.0f + __expf(-v[k]));
            si = fmaf(s, tv[k], si);
            sx = fmaf(s, s, sx);
            st = fmaf(tv[k], tv[k], st);
        }
    }

    __shared__ float sm[3][16];
    int lane = threadIdx.x & 31;
    int wid  = threadIdx.x >> 5;
    #pragma unroll
    for (int o = 16; o; o >>= 1) {
        si += __shfl_down_sync(0xffffffffu, si, o);
        sx += __shfl_down_sync(0xffffffffu, sx, o);
        st += __shfl_down_sync(0xffffffffu, st, o);
    }
    if (lane == 0) { sm[0][wid] = si; sm[1][wid] = sx; sm[2][wid] = st; }
    __syncthreads();
    if (wid == 0) {
        si = (lane < 16) ? sm[0][lane] : 0.0f;
        sx = (lane < 16) ? sm[1][lane] : 0.0f;
        st = (lane < 16) ? sm[2][lane] : 0.0f;
        #pragma unroll
        for (int o = 8; o; o >>= 1) {
            si += __shfl_down_sync(0xffffffffu, si, o);
            sx += __shfl_down_sync(0xffffffffu, sx, o);
            st += __shfl_down_sync(0xffffffffu, st, o);
        }
        if (lane == 0) {
            g_inter[inst] = si;
            g_ux[inst]    = sx;
            g_ut[inst]    = st;
        }
    }
}

__global__ __launch_bounds__(512) void loss_kernel(float* __restrict__ out, int n)
{
    __shared__ float sm[16];
    float acc = 0.0f;
    for (int i = threadIdx.x; i < n; i += 512) {
        float u = g_ux[i] + g_ut[i] + 1e-5f;
        acc += 1.0f - 2.0f * g_inter[i] / u;
    }
    int lane = threadIdx.x & 31;
    int wid  = threadIdx.x >> 5;
    #pragma unroll
    for (int o = 16; o; o >>= 1) acc += __shfl_down_sync(0xffffffffu, acc, o);
    if (lane == 0) sm[wid] = acc;
    __syncthreads();
    if (wid == 0) {
        acc = (lane < 16) ? sm[lane] : 0.0f;
        #pragma unroll
        for (int o = 8; o; o >>= 1) acc += __shfl_down_sync(0xffffffffu, acc, o);
        if (lane == 0) out[0] = acc / (float)n;
    }
}

extern "C" void kernel_launch(void* const* d_in, const int* in_sizes, int n_in,
                              void* d_out, int out_size)
{
    const float* feats   = (const float*)d_in[0];
    const float* params  = (const float*)d_in[1];
    const float* locs    = (const float*)d_in[2];
    const float* gt      = (const float*)d_in[3];
    const int*   im_inds = (const int*)d_in[4];
    const int*   fpn     = (const int*)d_in[5];

    int n = in_sizes[1] / NP;
    if (n > MAXI) n = MAXI;

    cudaFuncSetAttribute(dice_kernel, cudaFuncAttributeMaxDynamicSharedMemorySize,
                         HW * (int)sizeof(float));

    logits_kernel<<<BLKS_PER_INST * n, 256>>>(feats, params, locs, im_inds, fpn);
    dice_kernel<<<n, 512, HW * sizeof(float)>>>(gt);
    loss_kernel<<<1, 512>>>((float*)d_out, n);
}

// round 8
// speedup vs baseline: 1.5110x; 1.0227x over previous
#include <cuda_runtime.h>

#define Hh 100
#define Ww 136
#define HW (Hh * Ww)        // 13600
#define OH (2 * Hh)         // 200
#define OW (2 * Ww)         // 272
#define OHW (OH * OW)       // 54400
#define NP 169
#define MAXI 512
#define BLKS_PER_INST 8

typedef unsigned long long ull;

__device__ float g_logits[MAXI * HW];
__device__ float g_inter[MAXI];
__device__ float g_ux[MAXI];
__device__ float g_ut[MAXI];

// ---- packed f32x2 helpers (sm_100+) ----
__device__ __forceinline__ ull pk2(float lo, float hi) {
    ull r; asm("mov.b64 %0, {%1,%2};" : "=l"(r) : "f"(lo), "f"(hi)); return r;
}
__device__ __forceinline__ ull fma2(ull a, ull b, ull c) {
    ull d; asm("fma.rn.f32x2 %0, %1, %2, %3;" : "=l"(d) : "l"(a), "l"(b), "l"(c)); return d;
}
__device__ __forceinline__ ull mul2(ull a, ull b) {
    ull d; asm("mul.rn.f32x2 %0, %1, %2;" : "=l"(d) : "l"(a), "l"(b)); return d;
}
__device__ __forceinline__ ull add2(ull a, ull b) {
    ull d; asm("add.rn.f32x2 %0, %1, %2;" : "=l"(d) : "l"(a), "l"(b)); return d;
}
__device__ __forceinline__ ull relu2(ull a) {
    float x, y;
    asm("mov.b64 {%0,%1}, %2;" : "=f"(x), "=f"(y) : "l"(a));
    x = fmaxf(x, 0.0f); y = fmaxf(y, 0.0f);
    ull r; asm("mov.b64 %0, {%1,%2};" : "=l"(r) : "f"(x), "f"(y)); return r;
}
__device__ __forceinline__ void upk2(ull a, float& x, float& y) {
    asm("mov.b64 {%0,%1}, %2;" : "=f"(x), "=f"(y) : "l"(a));
}
__device__ __forceinline__ float tanh_fast(float x) {
    float r; asm("tanh.approx.f32 %0, %1;" : "=f"(r) : "f"(x)); return r;
}

// ---------------------------------------------------------------------------
// Kernel A: dynamic mask head -> logits. Layer-centric ILP=4 with per-
// iteration anti-pipelining barrier (R7, proven). NEW: each output's dot
// product split into two parallel chains (P: even ch from bias, Q: odd ch
// from mul) -> dep depth 10->5, 4 independent chains per thread.
// ---------------------------------------------------------------------------
__global__ __launch_bounds__(256, 2) void logits_kernel(
    const float* __restrict__ feats,
    const float* __restrict__ params,
    const float* __restrict__ locs,
    const int*   __restrict__ im_inds,
    const int*   __restrict__ fpn)
{
    const int inst = blockIdx.x / BLKS_PER_INST;
    const int part = blockIdx.x % BLKS_PER_INST;
    const int tid  = threadIdx.x;

    __shared__ __align__(16) ull sw0[8][12];   // [j][0..9]=w, [10]=bias
    __shared__ __align__(16) ull sw1[8][10];   // [j][0..7]=w, [8]=bias
    __shared__ __align__(16) ull sw2[10];      // [0..7]=w,   [8]=bias

    for (int i = tid; i < NP; i += 256) {
        float w = params[inst * NP + i];
        ull d = pk2(w, w);
        if      (i < 80)  sw0[i / 10][i % 10] = d;
        else if (i < 144) { int k = i - 80; sw1[k >> 3][k & 7] = d; }
        else if (i < 152) sw2[i - 144] = d;
        else if (i < 160) sw0[i - 152][10] = d;
        else if (i < 168) sw1[i - 160][8] = d;
        else              sw2[8] = d;
    }
    __syncthreads();

    const float cx = locs[inst * 2 + 0];
    const float cy = locs[inst * 2 + 1];
    const float inv_soi = 1.0f / (float)(8 << fpn[inst]);
    const float step = -8.0f * inv_soi;
    const float* __restrict__ fb = feats + (size_t)im_inds[inst] * 8 * HW;
    float* __restrict__ Lg = g_logits + (size_t)inst * HW;

    const int NQ   = HW / 4;                 // 3400 quads
    const int per  = NQ / BLKS_PER_INST;     // 425
    const int qbeg = part * per;
    const int qend = qbeg + per;

    for (int q = qbeg + tid; q < qend; q += 256) {
        const int p  = q * 4;
        const int py = p / Ww;
        const int px = p - py * Ww;
        const float dyv = (cy - (float)(py * 8 + 4)) * inv_soi;
        const float dxb = (cx - (float)(px * 8 + 4)) * inv_soi;
        const ull dy2 = pk2(dyv, dyv);
        const ull dx0 = pk2(dxb, dxb + step);
        const ull dx1 = pk2(dxb + 2.0f * step, dxb + 3.0f * step);

        ull f0[8], f1[8];
        #pragma unroll
        for (int c = 0; c < 8; c++) {
            float4 v = *(const float4*)&fb[c * HW + p];
            f0[c] = pk2(v.x, v.y);
            f1[c] = pk2(v.z, v.w);
        }

        // layer 0: 10 -> 8, relu. Split chains: P = bias+wy*dy+wx*dx+even f,
        // Q = odd f (mul-rooted). Depth 5-6 instead of 10.
        ull h0a[8], h0b[8];
        #pragma unroll
        for (int j = 0; j < 8; j++) {
            const ulonglong2* r = (const ulonglong2*)sw0[j];
            ulonglong2 wA = r[0], wB = r[1], wC = r[2], wD = r[3], wE = r[4];
            ull bias = sw0[j][10];
            ull ty = fma2(wA.y, dy2, bias);          // shared by both pairs
            // pair 0
            ull P0 = fma2(wA.x, dx0, ty);
            P0 = fma2(wB.x, f0[0], P0);
            P0 = fma2(wC.x, f0[2], P0);
            P0 = fma2(wD.x, f0[4], P0);
            P0 = fma2(wE.x, f0[6], P0);
            ull Q0 = mul2(wB.y, f0[1]);
            Q0 = fma2(wC.y, f0[3], Q0);
            Q0 = fma2(wD.y, f0[5], Q0);
            Q0 = fma2(wE.y, f0[7], Q0);
            // pair 1
            ull P1 = fma2(wA.x, dx1, ty);
            P1 = fma2(wB.x, f1[0], P1);
            P1 = fma2(wC.x, f1[2], P1);
            P1 = fma2(wD.x, f1[4], P1);
            P1 = fma2(wE.x, f1[6], P1);
            ull Q1 = mul2(wB.y, f1[1]);
            Q1 = fma2(wC.y, f1[3], Q1);
            Q1 = fma2(wD.y, f1[5], Q1);
            Q1 = fma2(wE.y, f1[7], Q1);
            h0a[j] = relu2(add2(P0, Q0));
            h0b[j] = relu2(add2(P1, Q1));
        }

        // layer 1: 8 -> 8, relu. Split chains.
        ull h1a[8], h1b[8];
        #pragma unroll
        for (int j = 0; j < 8; j++) {
            const ulonglong2* r = (const ulonglong2*)sw1[j];
            ulonglong2 wA = r[0], wB = r[1], wC = r[2], wD = r[3];
            ull bias = sw1[j][8];
            ull P0 = fma2(wA.x, h0a[0], bias);
            P0 = fma2(wB.x, h0a[2], P0);
            P0 = fma2(wC.x, h0a[4], P0);
            P0 = fma2(wD.x, h0a[6], P0);
            ull Q0 = mul2(wA.y, h0a[1]);
            Q0 = fma2(wB.y, h0a[3], Q0);
            Q0 = fma2(wC.y, h0a[5], Q0);
            Q0 = fma2(wD.y, h0a[7], Q0);
            ull P1 = fma2(wA.x, h0b[0], bias);
            P1 = fma2(wB.x, h0b[2], P1);
            P1 = fma2(wC.x, h0b[4], P1);
            P1 = fma2(wD.x, h0b[6], P1);
            ull Q1 = mul2(wA.y, h0b[1]);
            Q1 = fma2(wB.y, h0b[3], Q1);
            Q1 = fma2(wC.y, h0b[5], Q1);
            Q1 = fma2(wD.y, h0b[7], Q1);
            h1a[j] = relu2(add2(P0, Q0));
            h1b[j] = relu2(add2(P1, Q1));
        }

        // layer 2: 8 -> 1. Split chains.
        {
            const ulonglong2* r = (const ulonglong2*)sw2;
            ulonglong2 wA = r[0], wB = r[1], wC = r[2], wD = r[3];
            ull bias = sw2[8];
            ull P0 = fma2(wA.x, h1a[0], bias);
            P0 = fma2(wB.x, h1a[2], P0);
            P0 = fma2(wC.x, h1a[4], P0);
            P0 = fma2(wD.x, h1a[6], P0);
            ull Q0 = mul2(wA.y, h1a[1]);
            Q0 = fma2(wB.y, h1a[3], Q0);
            Q0 = fma2(wC.y, h1a[5], Q0);
            Q0 = fma2(wD.y, h1a[7], Q0);
            ull P1 = fma2(wA.x, h1b[0], bias);
            P1 = fma2(wB.x, h1b[2], P1);
            P1 = fma2(wC.x, h1b[4], P1);
            P1 = fma2(wD.x, h1b[6], P1);
            ull Q1 = mul2(wA.y, h1b[1]);
            Q1 = fma2(wB.y, h1b[3], Q1);
            Q1 = fma2(wC.y, h1b[5], Q1);
            Q1 = fma2(wD.y, h1b[7], Q1);
            ull a0 = add2(P0, Q0);
            ull a1 = add2(P1, Q1);
            float4 o;
            upk2(a0, o.x, o.y);
            upk2(a1, o.z, o.w);
            *(float4*)&Lg[p] = o;
        }

        // Anti-pipelining fence (R7 win: keeps regs ~120, no spill).
        asm volatile("" ::: "memory");
    }
}

// ---------------------------------------------------------------------------
// Kernel B: 2x aligned-bilinear + sigmoid(tanh) + dice partials.
// sigmoid via hardware tanh.approx: 1 MUFU instead of 2 (ex2+rcp).
// ---------------------------------------------------------------------------
__global__ __launch_bounds__(512) void dice_kernel(const float* __restrict__ gt)
{
    extern __shared__ float sL[];   // HW floats = 54.4 KB
    const int inst = blockIdx.x;
    const float* __restrict__ L = g_logits + (size_t)inst * HW;
    const float* __restrict__ T = gt + (size_t)inst * OHW;

    for (int i = threadIdx.x; i < HW; i += 512) sL[i] = L[i];
    __syncthreads();

    float si = 0.0f, sx = 0.0f, st = 0.0f;

    const int NQ = OHW / 4;
    for (int q = threadIdx.x; q < NQ; q += 512) {
        const int oy = q / (OW / 4);
        const int ox = (q - oy * (OW / 4)) * 4;
        const int j  = (oy > 0) ? (oy - 1) : 0;
        const int y0 = j >> 1;
        const int y1 = min(y0 + 1, Hh - 1);
        const float* r0 = sL + y0 * Ww;
        const float* r1 = sL + y1 * Ww;
        const bool vodd = (j & 1) != 0;

        const int i0 = (ox > 0) ? (ox - 1) : 0;
        float v[4];
        int ii[4] = { i0, ox, ox + 1, ox + 2 };
        if (!vodd) {
            #pragma unroll
            for (int k = 0; k < 4; k++) {
                int x0 = ii[k] >> 1;
                int x1 = min(x0 + 1, Ww - 1);
                float a = r0[x0];
                v[k] = (ii[k] & 1) ? 0.5f * (a + r0[x1]) : a;
            }
        } else {
            #pragma unroll
            for (int k = 0; k < 4; k++) {
                int x0 = ii[k] >> 1;
                int x1 = min(x0 + 1, Ww - 1);
                float a = r0[x0], b = r1[x0];
                v[k] = (ii[k] & 1) ? 0.25f * ((a + r0[x1]) + (b + r1[x1]))
                                   : 0.5f  * (a + b);
            }
        }

        const float4 t4 = __ldcs((const float4*)&T[oy * OW + ox]);
        const float tv[4] = { t4.x, t4.y, t4.z, t4.w };
        #pragma unroll
        for (int k = 0; k < 4; k++) {
            // sigmoid(v) = 0.5 + 0.5*tanh(v/2)  (1 MUFU)
            float s = fmaf(0.5f, tanh_fast(0.5f * v[k]), 0.5f);
            si = fmaf(s, tv[k], si);
            sx = fmaf(s, s, sx);
            st = fmaf(tv[k], tv[k], st);
        }
    }

    __shared__ float sm[3][16];
    int lane = threadIdx.x & 31;
    int wid  = threadIdx.x >> 5;
    #pragma unroll
    for (int o = 16; o; o >>= 1) {
        si += __shfl_down_sync(0xffffffffu, si, o);
        sx += __shfl_down_sync(0xffffffffu, sx, o);
        st += __shfl_down_sync(0xffffffffu, st, o);
    }
    if (lane == 0) { sm[0][wid] = si; sm[1][wid] = sx; sm[2][wid] = st; }
    __syncthreads();
    if (wid == 0) {
        si = (lane < 16) ? sm[0][lane] : 0.0f;
        sx = (lane < 16) ? sm[1][lane] : 0.0f;
        st = (lane < 16) ? sm[2][lane] : 0.0f;
        #pragma unroll
        for (int o = 8; o; o >>= 1) {
            si += __shfl_down_sync(0xffffffffu, si, o);
            sx += __shfl_down_sync(0xffffffffu, sx, o);
            st += __shfl_down_sync(0xffffffffu, st, o);
        }
        if (lane == 0) {
            g_inter[inst] = si;
            g_ux[inst]    = sx;
            g_ut[inst]    = st;
        }
    }
}

__global__ __launch_bounds__(512) void loss_kernel(float* __restrict__ out, int n)
{
    __shared__ float sm[16];
    float acc = 0.0f;
    for (int i = threadIdx.x; i < n; i += 512) {
        float u = g_ux[i] + g_ut[i] + 1e-5f;
        acc += 1.0f - 2.0f * g_inter[i] / u;
    }
    int lane = threadIdx.x & 31;
    int wid  = threadIdx.x >> 5;
    #pragma unroll
    for (int o = 16; o; o >>= 1) acc += __shfl_down_sync(0xffffffffu, acc, o);
    if (lane == 0) sm[wid] = acc;
    __syncthreads();
    if (wid == 0) {
        acc = (lane < 16) ? sm[lane] : 0.0f;
        #pragma unroll
        for (int o = 8; o; o >>= 1) acc += __shfl_down_sync(0xffffffffu, acc, o);
        if (lane == 0) out[0] = acc / (float)n;
    }
}

extern "C" void kernel_launch(void* const* d_in, const int* in_sizes, int n_in,
                              void* d_out, int out_size)
{
    const float* feats   = (const float*)d_in[0];
    const float* params  = (const float*)d_in[1];
    const float* locs    = (const float*)d_in[2];
    const float* gt      = (const float*)d_in[3];
    const int*   im_inds = (const int*)d_in[4];
    const int*   fpn     = (const int*)d_in[5];

    int n = in_sizes[1] / NP;
    if (n > MAXI) n = MAXI;

    cudaFuncSetAttribute(dice_kernel, cudaFuncAttributeMaxDynamicSharedMemorySize,
                         HW * (int)sizeof(float));

    logits_kernel<<<BLKS_PER_INST * n, 256>>>(feats, params, locs, im_inds, fpn);
    dice_kernel<<<n, 512, HW * sizeof(float)>>>(gt);
    loss_kernel<<<1, 512>>>((float*)d_out, n);
}

// round 9
// speedup vs baseline: 1.7500x; 1.1581x over previous
#include <cuda_runtime.h>

#define Hh 100
#define Ww 136
#define HW (Hh * Ww)        // 13600
#define OH (2 * Hh)         // 200
#define OW (2 * Ww)         // 272
#define OHW (OH * OW)       // 54400
#define NP 169
#define MAXI 512
#define BLKS_PER_INST 7

typedef unsigned long long ull;

__device__ float g_logits[MAXI * HW];
__device__ float g_inter[MAXI];
__device__ float g_ux[MAXI];
__device__ float g_ut[MAXI];

// ---- packed f32x2 helpers (sm_100+) ----
__device__ __forceinline__ ull pk2(float lo, float hi) {
    ull r; asm("mov.b64 %0, {%1,%2};" : "=l"(r) : "f"(lo), "f"(hi)); return r;
}
__device__ __forceinline__ ull fma2(ull a, ull b, ull c) {
    ull d; asm("fma.rn.f32x2 %0, %1, %2, %3;" : "=l"(d) : "l"(a), "l"(b), "l"(c)); return d;
}
__device__ __forceinline__ ull relu2(ull a) {
    float x, y;
    asm("mov.b64 {%0,%1}, %2;" : "=f"(x), "=f"(y) : "l"(a));
    x = fmaxf(x, 0.0f); y = fmaxf(y, 0.0f);
    ull r; asm("mov.b64 %0, {%1,%2};" : "=l"(r) : "f"(x), "f"(y)); return r;
}
__device__ __forceinline__ void upk2(ull a, float& x, float& y) {
    asm("mov.b64 {%0,%1}, %2;" : "=f"(x), "=f"(y) : "l"(a));
}
__device__ __forceinline__ float tanh_fast(float x) {
    float r; asm("tanh.approx.f32 %0, %1;" : "=f"(r) : "f"(x)); return r;
}

// ---------------------------------------------------------------------------
// Kernel A: dynamic mask head -> logits. R7 proven body (layer-centric ILP=4,
// single fma chains, per-iteration anti-pipelining barrier, 2 blocks/SM).
// NEW: 7 blocks/instance with per-instance grid-stride -> 2nd iteration 90%
// full (was 66%), empty warps exit early.
// ---------------------------------------------------------------------------
__global__ __launch_bounds__(256, 2) void logits_kernel(
    const float* __restrict__ feats,
    const float* __restrict__ params,
    const float* __restrict__ locs,
    const int*   __restrict__ im_inds,
    const int*   __restrict__ fpn)
{
    const int inst = blockIdx.x / BLKS_PER_INST;
    const int part = blockIdx.x % BLKS_PER_INST;
    const int tid  = threadIdx.x;

    __shared__ __align__(16) ull sw0[8][12];   // [j][0..9]=w, [10]=bias
    __shared__ __align__(16) ull sw1[8][10];   // [j][0..7]=w, [8]=bias
    __shared__ __align__(16) ull sw2[10];      // [0..7]=w,   [8]=bias

    for (int i = tid; i < NP; i += 256) {
        float w = params[inst * NP + i];
        ull d = pk2(w, w);
        if      (i < 80)  sw0[i / 10][i % 10] = d;
        else if (i < 144) { int k = i - 80; sw1[k >> 3][k & 7] = d; }
        else if (i < 152) sw2[i - 144] = d;
        else if (i < 160) sw0[i - 152][10] = d;
        else if (i < 168) sw1[i - 160][8] = d;
        else              sw2[8] = d;
    }
    __syncthreads();

    const float cx = locs[inst * 2 + 0];
    const float cy = locs[inst * 2 + 1];
    const float inv_soi = 1.0f / (float)(8 << fpn[inst]);
    const float step = -8.0f * inv_soi;
    const float* __restrict__ fb = feats + (size_t)im_inds[inst] * 8 * HW;
    float* __restrict__ Lg = g_logits + (size_t)inst * HW;

    const int NQ = HW / 4;   // 3400 quads (Ww%4==0)

    for (int q = part * 256 + tid; q < NQ; q += BLKS_PER_INST * 256) {
        const int p  = q * 4;
        const int py = p / Ww;
        const int px = p - py * Ww;
        const float dyv = (cy - (float)(py * 8 + 4)) * inv_soi;
        const float dxb = (cx - (float)(px * 8 + 4)) * inv_soi;
        const ull dy2 = pk2(dyv, dyv);
        const ull dx0 = pk2(dxb, dxb + step);
        const ull dx1 = pk2(dxb + 2.0f * step, dxb + 3.0f * step);

        ull f0[8], f1[8];
        #pragma unroll
        for (int c = 0; c < 8; c++) {
            float4 v = *(const float4*)&fb[c * HW + p];
            f0[c] = pk2(v.x, v.y);
            f1[c] = pk2(v.z, v.w);
        }

        // layer 0: 10 -> 8, relu
        ull h0a[8], h0b[8];
        #pragma unroll
        for (int j = 0; j < 8; j++) {
            const ulonglong2* r = (const ulonglong2*)sw0[j];
            ulonglong2 wA = r[0], wB = r[1], wC = r[2], wD = r[3], wE = r[4];
            ull bias = sw0[j][10];
            ull ty = fma2(wA.y, dy2, bias);
            ull a0 = fma2(wA.x, dx0, ty);
            ull a1 = fma2(wA.x, dx1, ty);
            a0 = fma2(wB.x, f0[0], a0);  a1 = fma2(wB.x, f1[0], a1);
            a0 = fma2(wB.y, f0[1], a0);  a1 = fma2(wB.y, f1[1], a1);
            a0 = fma2(wC.x, f0[2], a0);  a1 = fma2(wC.x, f1[2], a1);
            a0 = fma2(wC.y, f0[3], a0);  a1 = fma2(wC.y, f1[3], a1);
            a0 = fma2(wD.x, f0[4], a0);  a1 = fma2(wD.x, f1[4], a1);
            a0 = fma2(wD.y, f0[5], a0);  a1 = fma2(wD.y, f1[5], a1);
            a0 = fma2(wE.x, f0[6], a0);  a1 = fma2(wE.x, f1[6], a1);
            a0 = fma2(wE.y, f0[7], a0);  a1 = fma2(wE.y, f1[7], a1);
            h0a[j] = relu2(a0);
            h0b[j] = relu2(a1);
        }

        // layer 1: 8 -> 8, relu
        ull h1a[8], h1b[8];
        #pragma unroll
        for (int j = 0; j < 8; j++) {
            const ulonglong2* r = (const ulonglong2*)sw1[j];
            ulonglong2 wA = r[0], wB = r[1], wC = r[2], wD = r[3];
            ull bias = sw1[j][8];
            ull a0 = fma2(wA.x, h0a[0], bias);  ull a1 = fma2(wA.x, h0b[0], bias);
            a0 = fma2(wA.y, h0a[1], a0);  a1 = fma2(wA.y, h0b[1], a1);
            a0 = fma2(wB.x, h0a[2], a0);  a1 = fma2(wB.x, h0b[2], a1);
            a0 = fma2(wB.y, h0a[3], a0);  a1 = fma2(wB.y, h0b[3], a1);
            a0 = fma2(wC.x, h0a[4], a0);  a1 = fma2(wC.x, h0b[4], a1);
            a0 = fma2(wC.y, h0a[5], a0);  a1 = fma2(wC.y, h0b[5], a1);
            a0 = fma2(wD.x, h0a[6], a0);  a1 = fma2(wD.x, h0b[6], a1);
            a0 = fma2(wD.y, h0a[7], a0);  a1 = fma2(wD.y, h0b[7], a1);
            h1a[j] = relu2(a0);
            h1b[j] = relu2(a1);
        }

        // layer 2: 8 -> 1
        {
            const ulonglong2* r = (const ulonglong2*)sw2;
            ulonglong2 wA = r[0], wB = r[1], wC = r[2], wD = r[3];
            ull bias = sw2[8];
            ull a0 = fma2(wA.x, h1a[0], bias);  ull a1 = fma2(wA.x, h1b[0], bias);
            a0 = fma2(wA.y, h1a[1], a0);  a1 = fma2(wA.y, h1b[1], a1);
            a0 = fma2(wB.x, h1a[2], a0);  a1 = fma2(wB.x, h1b[2], a1);
            a0 = fma2(wB.y, h1a[3], a0);  a1 = fma2(wB.y, h1b[3], a1);
            a0 = fma2(wC.x, h1a[4], a0);  a1 = fma2(wC.x, h1b[4], a1);
            a0 = fma2(wC.y, h1a[5], a0);  a1 = fma2(wC.y, h1b[5], a1);
            a0 = fma2(wD.x, h1a[6], a0);  a1 = fma2(wD.x, h1b[6], a1);
            a0 = fma2(wD.y, h1a[7], a0);  a1 = fma2(wD.y, h1b[7], a1);
            float4 o;
            upk2(a0, o.x, o.y);
            upk2(a1, o.z, o.w);
            *(float4*)&Lg[p] = o;
        }

        // Anti-pipelining fence (R7 win: keeps regs ~120, no spill).
        asm volatile("" ::: "memory");
    }
}

// ---------------------------------------------------------------------------
// Kernel B: 2x aligned-bilinear + sigmoid(tanh) + dice partials.
// 3-tap quad form: an aligned output quad [ox..ox+3] needs only taps
// tL,tC,tR of the (row-averaged) logit row: v = {.5(tL+tC), tC, .5(tC+tR), tR}
// ---------------------------------------------------------------------------
__global__ __launch_bounds__(512) void dice_kernel(const float* __restrict__ gt)
{
    extern __shared__ float sL[];   // HW floats = 54.4 KB
    const int inst = blockIdx.x;
    const float* __restrict__ L = g_logits + (size_t)inst * HW;
    const float* __restrict__ T = gt + (size_t)inst * OHW;

    for (int i = threadIdx.x; i < HW; i += 512) sL[i] = L[i];
    __syncthreads();

    float si = 0.0f, sx = 0.0f, st = 0.0f;

    const int NQ = OHW / 4;            // 13600 quads, OW/4 = 68 per row
    for (int q = threadIdx.x; q < NQ; q += 512) {
        const int oy = q / (OW / 4);
        const int ox = (q - oy * (OW / 4)) * 4;
        const int j  = (oy > 0) ? (oy - 1) : 0;
        const int y0 = j >> 1;
        const int m  = ox >> 1;              // center tap col; m+1 <= 135 always
        const int ml = (m > 0) ? m - 1 : 0;
        const float* r0 = sL + y0 * Ww;

        float tL, tC, tR;
        if ((j & 1) == 0) {
            tL = r0[ml]; tC = r0[m]; tR = r0[m + 1];
        } else {
            const float* r1 = sL + min(y0 + 1, Hh - 1) * Ww;
            tL = 0.5f * (r0[ml] + r1[ml]);
            tC = 0.5f * (r0[m]  + r1[m]);
            tR = 0.5f * (r0[m + 1] + r1[m + 1]);
        }

        float v[4];
        v[0] = (ox > 0) ? 0.5f * (tL + tC) : tC;
        v[1] = tC;
        v[2] = 0.5f * (tC + tR);
        v[3] = tR;

        const float4 t4 = __ldcs((const float4*)&T[oy * OW + ox]);
        const float tv[4] = { t4.x, t4.y, t4.z, t4.w };
        #pragma unroll
        for (int k = 0; k < 4; k++) {
            float s = fmaf(0.5f, tanh_fast(0.5f * v[k]), 0.5f);   // sigmoid
            si = fmaf(s, tv[k], si);
            sx = fmaf(s, s, sx);
            st = fmaf(tv[k], tv[k], st);
        }
    }

    __shared__ float sm[3][16];
    int lane = threadIdx.x & 31;
    int wid  = threadIdx.x >> 5;
    #pragma unroll
    for (int o = 16; o; o >>= 1) {
        si += __shfl_down_sync(0xffffffffu, si, o);
        sx += __shfl_down_sync(0xffffffffu, sx, o);
        st += __shfl_down_sync(0xffffffffu, st, o);
    }
    if (lane == 0) { sm[0][wid] = si; sm[1][wid] = sx; sm[2][wid] = st; }
    __syncthreads();
    if (wid == 0) {
        si = (lane < 16) ? sm[0][lane] : 0.0f;
        sx = (lane < 16) ? sm[1][lane] : 0.0f;
        st = (lane < 16) ? sm[2][lane] : 0.0f;
        #pragma unroll
        for (int o = 8; o; o >>= 1) {
            si += __shfl_down_sync(0xffffffffu, si, o);
            sx += __shfl_down_sync(0xffffffffu, sx, o);
            st += __shfl_down_sync(0xffffffffu, st, o);
        }
        if (lane == 0) {
            g_inter[inst] = si;
            g_ux[inst]    = sx;
            g_ut[inst]    = st;
        }
    }
}

__global__ __launch_bounds__(512) void loss_kernel(float* __restrict__ out, int n)
{
    __shared__ float sm[16];
    float acc = 0.0f;
    for (int i = threadIdx.x; i < n; i += 512) {
        float u = g_ux[i] + g_ut[i] + 1e-5f;
        acc += 1.0f - 2.0f * g_inter[i] / u;
    }
    int lane = threadIdx.x & 31;
    int wid  = threadIdx.x >> 5;
    #pragma unroll
    for (int o = 16; o; o >>= 1) acc += __shfl_down_sync(0xffffffffu, acc, o);
    if (lane == 0) sm[wid] = acc;
    __syncthreads();
    if (wid == 0) {
        acc = (lane < 16) ? sm[lane] : 0.0f;
        #pragma unroll
        for (int o = 8; o; o >>= 1) acc += __shfl_down_sync(0xffffffffu, acc, o);
        if (lane == 0) out[0] = acc / (float)n;
    }
}

extern "C" void kernel_launch(void* const* d_in, const int* in_sizes, int n_in,
                              void* d_out, int out_size)
{
    const float* feats   = (const float*)d_in[0];
    const float* params  = (const float*)d_in[1];
    const float* locs    = (const float*)d_in[2];
    const float* gt      = (const float*)d_in[3];
    const int*   im_inds = (const int*)d_in[4];
    const int*   fpn     = (const int*)d_in[5];

    int n = in_sizes[1] / NP;
    if (n > MAXI) n = MAXI;

    cudaFuncSetAttribute(dice_kernel, cudaFuncAttributeMaxDynamicSharedMemorySize,
                         HW * (int)sizeof(float));

    logits_kernel<<<BLKS_PER_INST * n, 256>>>(feats, params, locs, im_inds, fpn);
    dice_kernel<<<n, 512, HW * sizeof(float)>>>(gt);
    loss_kernel<<<1, 512>>>((float*)d_out, n);
}

// round 10
// speedup vs baseline: 1.7913x; 1.0236x over previous
#include <cuda_runtime.h>

#define Hh 100
#define Ww 136
#define HW (Hh * Ww)        // 13600
#define OH (2 * Hh)         // 200
#define OW (2 * Ww)         // 272
#define OHW (OH * OW)       // 54400
#define NP 169
#define MAXI 512
#define NBANDS 4            // output-row bands per instance
#define BAND_OH 50          // output rows per band
#define MAX_ROWS 27         // max logit rows a band needs

typedef unsigned long long ull;

// per-(instance,band) dice partials
__device__ float g_pi[MAXI * NBANDS];
__device__ float g_px[MAXI * NBANDS];
__device__ float g_pt[MAXI * NBANDS];

// ---- packed f32x2 helpers (sm_100+) ----
__device__ __forceinline__ ull pk2(float lo, float hi) {
    ull r; asm("mov.b64 %0, {%1,%2};" : "=l"(r) : "f"(lo), "f"(hi)); return r;
}
__device__ __forceinline__ ull fma2(ull a, ull b, ull c) {
    ull d; asm("fma.rn.f32x2 %0, %1, %2, %3;" : "=l"(d) : "l"(a), "l"(b), "l"(c)); return d;
}
__device__ __forceinline__ ull relu2(ull a) {
    float x, y;
    asm("mov.b64 {%0,%1}, %2;" : "=f"(x), "=f"(y) : "l"(a));
    x = fmaxf(x, 0.0f); y = fmaxf(y, 0.0f);
    ull r; asm("mov.b64 %0, {%1,%2};" : "=l"(r) : "f"(x), "f"(y)); return r;
}
__device__ __forceinline__ void upk2(ull a, float& x, float& y) {
    asm("mov.b64 {%0,%1}, %2;" : "=f"(x), "=f"(y) : "l"(a));
}
__device__ __forceinline__ float tanh_fast(float x) {
    float r; asm("tanh.approx.f32 %0, %1;" : "=f"(r) : "f"(x)); return r;
}

// ---------------------------------------------------------------------------
// Fused kernel: one block = one (instance, band). Phase 1 computes the band's
// ~27 logit rows into SMEM (R7/R9 proven MLP body). Phase 2 does 2x aligned
// bilinear + sigmoid + dice partials for the band's 50 output rows straight
// from SMEM. No global logits round trip; co-resident blocks mix phases.
// ---------------------------------------------------------------------------
__global__ __launch_bounds__(256, 2) void fused_kernel(
    const float* __restrict__ feats,
    const float* __restrict__ params,
    const float* __restrict__ locs,
    const int*   __restrict__ im_inds,
    const int*   __restrict__ fpn,
    const float* __restrict__ gt)
{
    const int inst = blockIdx.x >> 2;
    const int band = blockIdx.x & 3;
    const int tid  = threadIdx.x;

    extern __shared__ float sL[];              // MAX_ROWS * Ww floats

    __shared__ __align__(16) ull sw0[8][12];   // [j][0..9]=w, [10]=bias
    __shared__ __align__(16) ull sw1[8][10];   // [j][0..7]=w, [8]=bias
    __shared__ __align__(16) ull sw2[10];      // [0..7]=w,   [8]=bias

    for (int i = tid; i < NP; i += 256) {
        float w = params[inst * NP + i];
        ull d = pk2(w, w);
        if      (i < 80)  sw0[i / 10][i % 10] = d;
        else if (i < 144) { int k = i - 80; sw1[k >> 3][k & 7] = d; }
        else if (i < 152) sw2[i - 144] = d;
        else if (i < 160) sw0[i - 152][10] = d;
        else if (i < 168) sw1[i - 160][8] = d;
        else              sw2[8] = d;
    }
    __syncthreads();

    // band geometry
    const int oy0  = band * BAND_OH;                       // first output row
    const int ry0  = (band > 0) ? (25 * band - 1) : 0;     // first logit row
    const int ry1  = (25 * band + 25 < Hh) ? (25 * band + 25) : (Hh - 1);
    const int nrows = ry1 - ry0 + 1;                       // 26 or 27

    const float cx = locs[inst * 2 + 0];
    const float cy = locs[inst * 2 + 1];
    const float inv_soi = 1.0f / (float)(8 << fpn[inst]);
    const float step = -8.0f * inv_soi;
    const float* __restrict__ fb = feats + (size_t)im_inds[inst] * 8 * HW;

    // ---------------- Phase 1: logits for rows [ry0..ry1] into SMEM --------
    const int NQ = nrows * (Ww / 4);        // <= 27*34 = 918 quads
    for (int q = tid; q < NQ; q += 256) {
        const int lr = q / (Ww / 4);
        const int px = (q - lr * (Ww / 4)) * 4;
        const int py = ry0 + lr;
        const int p  = py * Ww + px;
        const float dyv = (cy - (float)(py * 8 + 4)) * inv_soi;
        const float dxb = (cx - (float)(px * 8 + 4)) * inv_soi;
        const ull dy2 = pk2(dyv, dyv);
        const ull dx0 = pk2(dxb, dxb + step);
        const ull dx1 = pk2(dxb + 2.0f * step, dxb + 3.0f * step);

        ull f0[8], f1[8];
        #pragma unroll
        for (int c = 0; c < 8; c++) {
            float4 v = *(const float4*)&fb[c * HW + p];
            f0[c] = pk2(v.x, v.y);
            f1[c] = pk2(v.z, v.w);
        }

        // layer 0: 10 -> 8, relu
        ull h0a[8], h0b[8];
        #pragma unroll
        for (int j = 0; j < 8; j++) {
            const ulonglong2* r = (const ulonglong2*)sw0[j];
            ulonglong2 wA = r[0], wB = r[1], wC = r[2], wD = r[3], wE = r[4];
            ull bias = sw0[j][10];
            ull ty = fma2(wA.y, dy2, bias);
            ull a0 = fma2(wA.x, dx0, ty);
            ull a1 = fma2(wA.x, dx1, ty);
            a0 = fma2(wB.x, f0[0], a0);  a1 = fma2(wB.x, f1[0], a1);
            a0 = fma2(wB.y, f0[1], a0);  a1 = fma2(wB.y, f1[1], a1);
            a0 = fma2(wC.x, f0[2], a0);  a1 = fma2(wC.x, f1[2], a1);
            a0 = fma2(wC.y, f0[3], a0);  a1 = fma2(wC.y, f1[3], a1);
            a0 = fma2(wD.x, f0[4], a0);  a1 = fma2(wD.x, f1[4], a1);
            a0 = fma2(wD.y, f0[5], a0);  a1 = fma2(wD.y, f1[5], a1);
            a0 = fma2(wE.x, f0[6], a0);  a1 = fma2(wE.x, f1[6], a1);
            a0 = fma2(wE.y, f0[7], a0);  a1 = fma2(wE.y, f1[7], a1);
            h0a[j] = relu2(a0);
            h0b[j] = relu2(a1);
        }

        // layer 1: 8 -> 8, relu
        ull h1a[8], h1b[8];
        #pragma unroll
        for (int j = 0; j < 8; j++) {
            const ulonglong2* r = (const ulonglong2*)sw1[j];
            ulonglong2 wA = r[0], wB = r[1], wC = r[2], wD = r[3];
            ull bias = sw1[j][8];
            ull a0 = fma2(wA.x, h0a[0], bias);  ull a1 = fma2(wA.x, h0b[0], bias);
            a0 = fma2(wA.y, h0a[1], a0);  a1 = fma2(wA.y, h0b[1], a1);
            a0 = fma2(wB.x, h0a[2], a0);  a1 = fma2(wB.x, h0b[2], a1);
            a0 = fma2(wB.y, h0a[3], a0);  a1 = fma2(wB.y, h0b[3], a1);
            a0 = fma2(wC.x, h0a[4], a0);  a1 = fma2(wC.x, h0b[4], a1);
            a0 = fma2(wC.y, h0a[5], a0);  a1 = fma2(wC.y, h0b[5], a1);
            a0 = fma2(wD.x, h0a[6], a0);  a1 = fma2(wD.x, h0b[6], a1);
            a0 = fma2(wD.y, h0a[7], a0);  a1 = fma2(wD.y, h0b[7], a1);
            h1a[j] = relu2(a0);
            h1b[j] = relu2(a1);
        }

        // layer 2: 8 -> 1
        {
            const ulonglong2* r = (const ulonglong2*)sw2;
            ulonglong2 wA = r[0], wB = r[1], wC = r[2], wD = r[3];
            ull bias = sw2[8];
            ull a0 = fma2(wA.x, h1a[0], bias);  ull a1 = fma2(wA.x, h1b[0], bias);
            a0 = fma2(wA.y, h1a[1], a0);  a1 = fma2(wA.y, h1b[1], a1);
            a0 = fma2(wB.x, h1a[2], a0);  a1 = fma2(wB.x, h1b[2], a1);
            a0 = fma2(wB.y, h1a[3], a0);  a1 = fma2(wB.y, h1b[3], a1);
            a0 = fma2(wC.x, h1a[4], a0);  a1 = fma2(wC.x, h1b[4], a1);
            a0 = fma2(wC.y, h1a[5], a0);  a1 = fma2(wC.y, h1b[5], a1);
            a0 = fma2(wD.x, h1a[6], a0);  a1 = fma2(wD.x, h1b[6], a1);
            a0 = fma2(wD.y, h1a[7], a0);  a1 = fma2(wD.y, h1b[7], a1);
            float4 o;
            upk2(a0, o.x, o.y);
            upk2(a1, o.z, o.w);
            *(float4*)&sL[lr * Ww + px] = o;
        }

        // Anti-pipelining fence (R7 win: keeps regs bounded, no spill).
        asm volatile("" ::: "memory");
    }
    __syncthreads();

    // ---------------- Phase 2: bilinear + sigmoid + dice on the band -------
    const float* __restrict__ T = gt + (size_t)inst * OHW;
    float si = 0.0f, sx = 0.0f, st = 0.0f;

    // 8-px units: 50 rows * 34 units = 1700 per block
    const int NU = BAND_OH * (OW / 8);
    for (int u = tid; u < NU; u += 256) {
        const int r   = u / (OW / 8);
        const int ox8 = (u - r * (OW / 8)) * 8;
        const int oy  = oy0 + r;
        const int j   = (oy > 0) ? (oy - 1) : 0;
        const int y0g = j >> 1;
        const float* r0 = sL + (y0g - ry0) * Ww;

        const int m0 = ox8 >> 1;                 // center tap col; m0+3 <= 135
        const int ml = (m0 > 0) ? m0 - 1 : 0;

        float t0, t1, t2, t3, t4;                // taps m0-1 .. m0+3
        if ((j & 1) == 0) {
            t0 = r0[ml]; t1 = r0[m0]; t2 = r0[m0 + 1]; t3 = r0[m0 + 2]; t4 = r0[m0 + 3];
        } else {
            const int y1g = (y0g + 1 < Hh) ? y0g + 1 : Hh - 1;
            const float* r1 = sL + (y1g - ry0) * Ww;
            t0 = 0.5f * (r0[ml]     + r1[ml]);
            t1 = 0.5f * (r0[m0]     + r1[m0]);
            t2 = 0.5f * (r0[m0 + 1] + r1[m0 + 1]);
            t3 = 0.5f * (r0[m0 + 2] + r1[m0 + 2]);
            t4 = 0.5f * (r0[m0 + 3] + r1[m0 + 3]);
        }

        float v[8];
        v[0] = (ox8 > 0) ? 0.5f * (t0 + t1) : t1;
        v[1] = t1;
        v[2] = 0.5f * (t1 + t2);
        v[3] = t2;
        v[4] = 0.5f * (t2 + t3);
        v[5] = t3;
        v[6] = 0.5f * (t3 + t4);
        v[7] = t4;

        const float4 ta = __ldcs((const float4*)&T[oy * OW + ox8]);
        const float4 tb = __ldcs((const float4*)&T[oy * OW + ox8 + 4]);
        const float tv[8] = { ta.x, ta.y, ta.z, ta.w, tb.x, tb.y, tb.z, tb.w };
        #pragma unroll
        for (int k = 0; k < 8; k++) {
            float s = fmaf(0.5f, tanh_fast(0.5f * v[k]), 0.5f);   // sigmoid
            si = fmaf(s, tv[k], si);
            sx = fmaf(s, s, sx);
            st = fmaf(tv[k], tv[k], st);
        }
    }

    // block reduction (8 warps) -> per-(inst,band) partials
    __shared__ float sm[3][8];
    int lane = tid & 31;
    int wid  = tid >> 5;
    #pragma unroll
    for (int o = 16; o; o >>= 1) {
        si += __shfl_down_sync(0xffffffffu, si, o);
        sx += __shfl_down_sync(0xffffffffu, sx, o);
        st += __shfl_down_sync(0xffffffffu, st, o);
    }
    if (lane == 0) { sm[0][wid] = si; sm[1][wid] = sx; sm[2][wid] = st; }
    __syncthreads();
    if (wid == 0) {
        si = (lane < 8) ? sm[0][lane] : 0.0f;
        sx = (lane < 8) ? sm[1][lane] : 0.0f;
        st = (lane < 8) ? sm[2][lane] : 0.0f;
        #pragma unroll
        for (int o = 4; o; o >>= 1) {
            si += __shfl_down_sync(0xffffffffu, si, o);
            sx += __shfl_down_sync(0xffffffffu, sx, o);
            st += __shfl_down_sync(0xffffffffu, st, o);
        }
        if (lane == 0) {
            g_pi[blockIdx.x] = si;
            g_px[blockIdx.x] = sx;
            g_pt[blockIdx.x] = st;
        }
    }
}

// ---------------------------------------------------------------------------
// Loss: sum the 4 band partials per instance (deterministic), dice, mean.
// ---------------------------------------------------------------------------
__global__ __launch_bounds__(512) void loss_kernel(float* __restrict__ out, int n)
{
    __shared__ float sm[16];
    float acc = 0.0f;
    for (int i = threadIdx.x; i < n; i += 512) {
        float si = 0.0f, sx = 0.0f, st = 0.0f;
        #pragma unroll
        for (int b = 0; b < NBANDS; b++) {
            si += g_pi[i * NBANDS + b];
            sx += g_px[i * NBANDS + b];
            st += g_pt[i * NBANDS + b];
        }
        float u = sx + st + 1e-5f;
        acc += 1.0f - 2.0f * si / u;
    }
    int lane = threadIdx.x & 31;
    int wid  = threadIdx.x >> 5;
    #pragma unroll
    for (int o = 16; o; o >>= 1) acc += __shfl_down_sync(0xffffffffu, acc, o);
    if (lane == 0) sm[wid] = acc;
    __syncthreads();
    if (wid == 0) {
        acc = (lane < 16) ? sm[lane] : 0.0f;
        #pragma unroll
        for (int o = 8; o; o >>= 1) acc += __shfl_down_sync(0xffffffffu, acc, o);
        if (lane == 0) out[0] = acc / (float)n;
    }
}

extern "C" void kernel_launch(void* const* d_in, const int* in_sizes, int n_in,
                              void* d_out, int out_size)
{
    const float* feats   = (const float*)d_in[0];
    const float* params  = (const float*)d_in[1];
    const float* locs    = (const float*)d_in[2];
    const float* gt      = (const float*)d_in[3];
    const int*   im_inds = (const int*)d_in[4];
    const int*   fpn     = (const int*)d_in[5];

    int n = in_sizes[1] / NP;
    if (n > MAXI) n = MAXI;

    const int smem = MAX_ROWS * Ww * (int)sizeof(float);   // 14688 B

    fused_kernel<<<NBANDS * n, 256, smem>>>(feats, params, locs, im_inds, fpn, gt);
    loss_kernel<<<1, 512>>>((float*)d_out, n);
}